// round 1
// baseline (speedup 1.0000x reference)
#include <cuda_runtime.h>
#include <math.h>

#define N_PTS 1000000
#define G     256
#define H1C   64
#define H2C   128
#define LAT   256
#define TILE  64
#define NT    (N_PTS / TILE)   // 15625 exactly

// ---------------- scratch (device globals; no allocations allowed) ----------
__device__ unsigned g_pooled[G * LAT];   // order-preserving encoded float max
__device__ float    g_csum[G * 3];
__device__ float    g_cnt[G];
__device__ int      g_tile;

// order-preserving float<->uint encoding for atomicMax on floats (any sign)
__device__ __forceinline__ unsigned encf(float f) {
    unsigned u = __float_as_uint(f);
    return (u & 0x80000000u) ? ~u : (u | 0x80000000u);
}
__device__ __forceinline__ float decf(unsigned u) {
    return (u & 0x80000000u) ? __uint_as_float(u ^ 0x80000000u)
                             : __uint_as_float(~u);
}

__device__ __forceinline__ float softplus_f(float x) {
    // log1p(exp(x)) stable both directions
    return fmaxf(x, 0.f) + log1pf(expf(-fabsf(x)));
}

// ---------------- shared memory layout for the MLP kernel -------------------
struct SmemT {
    float W3s[H2C * LAT];   // 128*256 = 32768 f (128 KB)
    float W2s[H1C * H2C];   // 64*128  =  8192 f (32 KB)
    float W1s[4 * H1C];     // 256 f
    float b1s[H1C];
    float b2s[H2C];
    float b3s[LAT];
    float h1s[TILE * H1C];  // 4096 f (16 KB); reused as reduction buffer
    float h2s[TILE * H2C];  // 8192 f (32 KB)
    float feats[TILE * 4];
    int   segs[TILE];
    int   tile;
};

// ---------------- kernels ---------------------------------------------------
__global__ void k_init() {
    int i = blockIdx.x * blockDim.x + threadIdx.x;
    int stride = gridDim.x * blockDim.x;
    for (int j = i; j < G * LAT; j += stride) g_pooled[j] = 0u;  // < any encoded value
    if (i < G * 3) g_csum[i] = 0.f;
    if (i < G)     g_cnt[i]  = 0.f;
    if (i == 0)    g_tile    = 0;
}

// seg_ids sorted -> warps are almost always single-segment: 1 atomic set / warp
__global__ void k_centroid(const float* __restrict__ pc,
                           const int*   __restrict__ seg) {
    const bool is64 = (seg[N_PTS - 1] == 0);   // int64 high word vs last id==255
    int p = blockIdx.x * blockDim.x + threadIdx.x;   // grid covers exactly N
    float x = pc[(size_t)p * 5 + 1];
    float y = pc[(size_t)p * 5 + 2];
    float z = pc[(size_t)p * 5 + 3];
    int s = is64 ? seg[2 * p] : seg[p];
    int s0 = __shfl_sync(0xffffffffu, s, 0);
    if (__all_sync(0xffffffffu, s == s0)) {
        #pragma unroll
        for (int o = 16; o > 0; o >>= 1) {
            x += __shfl_down_sync(0xffffffffu, x, o);
            y += __shfl_down_sync(0xffffffffu, y, o);
            z += __shfl_down_sync(0xffffffffu, z, o);
        }
        if ((threadIdx.x & 31) == 0) {
            atomicAdd(&g_csum[s * 3 + 0], x);
            atomicAdd(&g_csum[s * 3 + 1], y);
            atomicAdd(&g_csum[s * 3 + 2], z);
            atomicAdd(&g_cnt[s], 32.f);
        }
    } else {
        atomicAdd(&g_csum[s * 3 + 0], x);
        atomicAdd(&g_csum[s * 3 + 1], y);
        atomicAdd(&g_csum[s * 3 + 2], z);
        atomicAdd(&g_cnt[s], 1.f);
    }
}

__global__ __launch_bounds__(256, 1)
void k_mlp(const float* __restrict__ pc,
           const float* __restrict__ W1, const float* __restrict__ b1,
           const float* __restrict__ W2, const float* __restrict__ b2,
           const float* __restrict__ W3, const float* __restrict__ b3,
           const int*   __restrict__ seg) {
    extern __shared__ char raw[];
    SmemT* S = (SmemT*)raw;
    const int tid = threadIdx.x;
    const bool is64 = (seg[N_PTS - 1] == 0);

    // one-time weight load (persistent CTA)
    for (int i = tid; i < H2C * LAT; i += 256) S->W3s[i] = W3[i];
    for (int i = tid; i < H1C * H2C; i += 256) S->W2s[i] = W2[i];
    for (int i = tid; i < 4 * H1C;   i += 256) S->W1s[i] = W1[i];
    for (int i = tid; i < H1C;       i += 256) S->b1s[i] = b1[i];
    for (int i = tid; i < H2C;       i += 256) S->b2s[i] = b2[i];
    for (int i = tid; i < LAT;       i += 256) S->b3s[i] = b3[i];

    const int col = tid & 31;   // n = col + 32*j (strided, conflict-free)
    const int rg  = tid >> 5;   // row group: points rg*8 .. rg*8+7

    for (;;) {
        __syncthreads();        // protects smem reuse across tiles
        if (tid == 0) S->tile = atomicAdd(&g_tile, 1);
        __syncthreads();
        const int t = S->tile;
        if (t >= NT) break;
        const int P0 = t * TILE;

        // load tile feats ([x, pos]) and segment ids
        for (int i = tid; i < TILE * 5; i += 256) {
            int p = i / 5, c = i - p * 5;
            float v = pc[(size_t)(P0 + p) * 5 + c];
            if (c) {
                int k = (c == 4) ? 0 : c;  // feats = [x(col4), pos(col1..3)]
                S->feats[p * 4 + k] = v;
            }
        }
        if (tid < TILE) S->segs[tid] = is64 ? seg[2 * (P0 + tid)] : seg[P0 + tid];
        __syncthreads();

        // ---- layer 1: 64x4 @ 4x64 + relu -> h1s
        for (int idx = tid; idx < TILE * H1C; idx += 256) {
            int p = idx >> 6, n = idx & 63;
            float s = S->b1s[n];
            #pragma unroll
            for (int k = 0; k < 4; k++)
                s = fmaf(S->feats[p * 4 + k], S->W1s[k * H1C + n], s);
            S->h1s[p * H1C + n] = fmaxf(s, 0.f);
        }
        __syncthreads();

        // ---- layer 2: 64x64 @ 64x128 + relu -> h2s  (thread tile 8p x 4n)
        {
            float acc[8][4];
            #pragma unroll
            for (int r = 0; r < 8; r++)
                #pragma unroll
                for (int j = 0; j < 4; j++) acc[r][j] = 0.f;
            for (int k = 0; k < H1C; k += 4) {
                float4 a[8];
                #pragma unroll
                for (int r = 0; r < 8; r++)
                    a[r] = *(const float4*)&S->h1s[(rg * 8 + r) * H1C + k];
                #pragma unroll
                for (int kk = 0; kk < 4; kk++) {
                    float bb[4];
                    #pragma unroll
                    for (int j = 0; j < 4; j++)
                        bb[j] = S->W2s[(k + kk) * H2C + col + 32 * j];
                    #pragma unroll
                    for (int r = 0; r < 8; r++) {
                        float av = ((const float*)&a[r])[kk];
                        #pragma unroll
                        for (int j = 0; j < 4; j++)
                            acc[r][j] = fmaf(av, bb[j], acc[r][j]);
                    }
                }
            }
            #pragma unroll
            for (int r = 0; r < 8; r++)
                #pragma unroll
                for (int j = 0; j < 4; j++)
                    S->h2s[(rg * 8 + r) * H2C + col + 32 * j] =
                        fmaxf(acc[r][j] + S->b2s[col + 32 * j], 0.f);
        }
        __syncthreads();

        // ---- layer 3: 64x128 @ 128x256 (no relu)  (thread tile 8p x 8n)
        float acc3[8][8];
        #pragma unroll
        for (int r = 0; r < 8; r++)
            #pragma unroll
            for (int j = 0; j < 8; j++) acc3[r][j] = 0.f;
        for (int k = 0; k < H2C; k += 4) {
            float4 a[8];
            #pragma unroll
            for (int r = 0; r < 8; r++)
                a[r] = *(const float4*)&S->h2s[(rg * 8 + r) * H2C + k];
            #pragma unroll
            for (int kk = 0; kk < 4; kk++) {
                float bb[8];
                #pragma unroll
                for (int j = 0; j < 8; j++)
                    bb[j] = S->W3s[(k + kk) * LAT + col + 32 * j];
                #pragma unroll
                for (int r = 0; r < 8; r++) {
                    float av = ((const float*)&a[r])[kk];
                    #pragma unroll
                    for (int j = 0; j < 8; j++)
                        acc3[r][j] = fmaf(av, bb[j], acc3[r][j]);
                }
            }
        }

        // ---- segment max pooling (bias folded in at reduction)
        const int s0 = S->segs[0], s63 = S->segs[TILE - 1];
        if (s0 == s63) {
            // single-segment tile (common: seg_ids sorted): block-wide reduce,
            // 256 atomics/tile total
            #pragma unroll
            for (int j = 0; j < 8; j++) {
                float m = -3.402823466e38f;
                #pragma unroll
                for (int r = 0; r < 8; r++) m = fmaxf(m, acc3[r][j]);
                S->h1s[rg * 256 + j * 32 + col] = m + S->b3s[col + 32 * j];
            }
            __syncthreads();
            if (tid < 32) {
                #pragma unroll
                for (int j = 0; j < 8; j++) {
                    float m = -3.402823466e38f;
                    #pragma unroll
                    for (int rr = 0; rr < 8; rr++)
                        m = fmaxf(m, S->h1s[rr * 256 + j * 32 + tid]);
                    atomicMax(&g_pooled[s0 * LAT + j * 32 + tid], encf(m));
                }
            }
        } else {
            // boundary tile: per-rowgroup segmented flush
            int cur = S->segs[rg * 8];
            float vm[8];
            #pragma unroll
            for (int j = 0; j < 8; j++) vm[j] = -3.402823466e38f;
            #pragma unroll
            for (int r = 0; r < 8; r++) {
                int ss = S->segs[rg * 8 + r];
                if (ss != cur) {
                    #pragma unroll
                    for (int j = 0; j < 8; j++) {
                        atomicMax(&g_pooled[cur * LAT + col + 32 * j],
                                  encf(vm[j] + S->b3s[col + 32 * j]));
                        vm[j] = -3.402823466e38f;
                    }
                    cur = ss;
                }
                #pragma unroll
                for (int j = 0; j < 8; j++) vm[j] = fmaxf(vm[j], acc3[r][j]);
            }
            #pragma unroll
            for (int j = 0; j < 8; j++)
                atomicMax(&g_pooled[cur * LAT + col + 32 * j],
                          encf(vm[j] + S->b3s[col + 32 * j]));
        }
    }
}

__global__ void k_final(const float* __restrict__ Wf,
                        const float* __restrict__ bf,
                        float* __restrict__ out) {
    __shared__ float Wfs[LAT * 3];
    __shared__ float bfs[3];
    int g = threadIdx.x;
    for (int i = g; i < LAT * 3; i += 256) Wfs[i] = Wf[i];
    if (g < 3) bfs[g] = bf[g];
    __syncthreads();

    float cnt = g_cnt[g];
    float inv = 1.f / fmaxf(cnt, 1.f);
    float a0 = bfs[0], a1 = bfs[1], a2 = bfs[2];
    for (int j = 0; j < LAT; j++) {
        float v = decf(g_pooled[g * LAT + j]);
        a0 = fmaf(v, Wfs[j * 3 + 0], a0);
        a1 = fmaf(v, Wfs[j * 3 + 1], a1);
        a2 = fmaf(v, Wfs[j * 3 + 2], a2);
    }
    out[g * 3 + 0] = g_csum[g * 3 + 0] * inv + softplus_f(a0);
    out[g * 3 + 1] = g_csum[g * 3 + 1] * inv + softplus_f(a1);
    out[g * 3 + 2] = g_csum[g * 3 + 2] * inv + softplus_f(a2);
}

// ---------------- launch ----------------------------------------------------
extern "C" void kernel_launch(void* const* d_in, const int* in_sizes, int n_in,
                              void* d_out, int out_size) {
    const float* pc = (const float*)d_in[0];
    const float* W1 = (const float*)d_in[1];
    const float* b1 = (const float*)d_in[2];
    const float* W2 = (const float*)d_in[3];
    const float* b2 = (const float*)d_in[4];
    const float* W3 = (const float*)d_in[5];
    const float* b3 = (const float*)d_in[6];
    const float* Wf = (const float*)d_in[7];
    const float* bf = (const float*)d_in[8];
    const int*   sg = (const int*)d_in[9];
    float* out = (float*)d_out;

    (void)in_sizes; (void)n_in; (void)out_size;

    cudaFuncSetAttribute(k_mlp, cudaFuncAttributeMaxDynamicSharedMemorySize,
                         (int)sizeof(SmemT));
    int sms = 148;
    cudaDeviceGetAttribute(&sms, cudaDevAttrMultiProcessorCount, 0);

    k_init<<<64, 256>>>();
    k_centroid<<<3125, 320>>>(pc, sg);                       // 3125*320 == N
    k_mlp<<<sms, 256, sizeof(SmemT)>>>(pc, W1, b1, W2, b2, W3, b3, sg);
    k_final<<<1, 256>>>(Wf, bf, out);
}

// round 3
// speedup vs baseline: 2.7859x; 2.7859x over previous
#include <cuda_runtime.h>
#include <cuda_bf16.h>
#include <cstdint>
#include <math.h>

#define N_PTS 1000000
#define G     256
#define H1C   64
#define H2C   128
#define LAT   256
#define TILE  64
#define NT    15625         // 1e6 / 64 exactly

// ---------------- scratch -----------------------------------------------
__device__ unsigned g_pooled[G * LAT];
__device__ float    g_csum[G * 3];
__device__ float    g_cnt[G];
__device__ int      g_tile;

__device__ __forceinline__ unsigned encf(float f) {
    unsigned u = __float_as_uint(f);
    return (u & 0x80000000u) ? ~u : (u | 0x80000000u);
}
__device__ __forceinline__ float decf(unsigned u) {
    return (u & 0x80000000u) ? __uint_as_float(u ^ 0x80000000u)
                             : __uint_as_float(~u);
}
__device__ __forceinline__ float softplus_f(float x) {
    return fmaxf(x, 0.f) + log1pf(expf(-fabsf(x)));
}

// ---------------- mma.sync helpers (base sm_103-legal) -------------------
__device__ __forceinline__ uint32_t smem_u32(const void* p) {
    uint32_t a;
    asm("{ .reg .u64 t; cvta.to.shared.u64 t, %1; cvt.u32.u64 %0, t; }"
        : "=r"(a) : "l"(p));
    return a;
}
__device__ __forceinline__ void ldsm4(uint32_t r[4], uint32_t a) {
    asm volatile("ldmatrix.sync.aligned.m8n8.x4.shared.b16 {%0,%1,%2,%3}, [%4];"
        : "=r"(r[0]), "=r"(r[1]), "=r"(r[2]), "=r"(r[3]) : "r"(a));
}
__device__ __forceinline__ void mma16816(float d[4], const uint32_t a[4],
                                         uint32_t b0, uint32_t b1) {
    asm volatile(
        "mma.sync.aligned.m16n8k16.row.col.f32.bf16.bf16.f32 "
        "{%0,%1,%2,%3}, {%4,%5,%6,%7}, {%8,%9}, {%0,%1,%2,%3};"
        : "+f"(d[0]), "+f"(d[1]), "+f"(d[2]), "+f"(d[3])
        : "r"(a[0]), "r"(a[1]), "r"(a[2]), "r"(a[3]), "r"(b0), "r"(b1));
}
__device__ __forceinline__ unsigned pack_bf16(float lo, float hi) {
    unsigned r;
    asm("cvt.rn.bf16x2.f32 %0, %1, %2;" : "=r"(r) : "f"(hi), "f"(lo));
    return r;  // low 16 bits = lo arg
}
__device__ __forceinline__ float bf16_round(float v) {
    return __bfloat162float(__float2bfloat16(v));
}

// ---------------- SMEM layout (bytes; all tiles 1024-aligned) ------------
// W tiles stored [n-row][k-col], 128B rows, SW128 swizzle; k>=64 in block 2.
#define OFF_W3HI  0         // 2 blocks x 256 x 128B = 65536
#define OFF_W3LO  65536
#define OFF_W2HI  131072    // 128 x 128B = 16384
#define OFF_W2LO  147456
#define OFF_H1HI  163840    // 64 x 128B = 8192
#define OFF_H1LO  172032
#define OFF_H2HI  180224    // 2 blocks x 64 x 128B = 16384
#define OFF_H2LO  196608
#define OFF_FEATS 212992    // 64*4 f
#define OFF_W1    214016    // 256 f
#define OFF_B1    215040
#define OFF_B2    215296
#define OFF_B3    215808
#define OFF_SEGS  216832
#define OFF_TILE  217088
#define SMEM_TOTAL 217600

// ---------------- kernels ------------------------------------------------
__global__ void k_init() {
    int i = blockIdx.x * blockDim.x + threadIdx.x;
    int stride = gridDim.x * blockDim.x;
    for (int j = i; j < G * LAT; j += stride) g_pooled[j] = 0u;
    if (i < G * 3) g_csum[i] = 0.f;
    if (i < G)     g_cnt[i]  = 0.f;
    if (i == 0)    g_tile    = 0;
}

__global__ void k_centroid(const float* __restrict__ pc,
                           const int*   __restrict__ seg) {
    const bool is64 = (seg[N_PTS - 1] == 0);
    int p = blockIdx.x * blockDim.x + threadIdx.x;
    float x = pc[(size_t)p * 5 + 1];
    float y = pc[(size_t)p * 5 + 2];
    float z = pc[(size_t)p * 5 + 3];
    int s = is64 ? seg[2 * p] : seg[p];
    int s0 = __shfl_sync(0xffffffffu, s, 0);
    if (__all_sync(0xffffffffu, s == s0)) {
        #pragma unroll
        for (int o = 16; o > 0; o >>= 1) {
            x += __shfl_down_sync(0xffffffffu, x, o);
            y += __shfl_down_sync(0xffffffffu, y, o);
            z += __shfl_down_sync(0xffffffffu, z, o);
        }
        if ((threadIdx.x & 31) == 0) {
            atomicAdd(&g_csum[s * 3 + 0], x);
            atomicAdd(&g_csum[s * 3 + 1], y);
            atomicAdd(&g_csum[s * 3 + 2], z);
            atomicAdd(&g_cnt[s], 32.f);
        }
    } else {
        atomicAdd(&g_csum[s * 3 + 0], x);
        atomicAdd(&g_csum[s * 3 + 1], y);
        atomicAdd(&g_csum[s * 3 + 2], z);
        atomicAdd(&g_cnt[s], 1.f);
    }
}

__global__ __launch_bounds__(256, 1)
void k_mlp(const float* __restrict__ pc,
           const float* __restrict__ W1, const float* __restrict__ b1,
           const float* __restrict__ W2, const float* __restrict__ b2,
           const float* __restrict__ W3, const float* __restrict__ b3,
           const int*   __restrict__ seg) {
    extern __shared__ __align__(1024) char smem[];
    const uint32_t sb = smem_u32(smem);
    const int tid  = threadIdx.x;
    const int w    = tid >> 5;
    const int lane = tid & 31;
    const bool is64 = (seg[N_PTS - 1] == 0);

    float* feats = (float*)(smem + OFF_FEATS);
    float* W1s   = (float*)(smem + OFF_W1);
    float* b1s   = (float*)(smem + OFF_B1);
    float* b2s   = (float*)(smem + OFF_B2);
    float* b3s   = (float*)(smem + OFF_B3);
    int*   segs  = (int*)  (smem + OFF_SEGS);

    // ---- one-time weight prep: transpose to [n][k], bf16 hi/lo, SW128 ----
    for (int i = tid; i < H1C * H2C; i += 256) {          // W2 [k=64][n=128]
        int k = i >> 7, n = i & 127;
        float v = W2[i];
        unsigned off = (unsigned)(n * 128) + (((unsigned)(k * 2)) ^ ((n & 7) << 4));
        *(__nv_bfloat16*)(smem + OFF_W2HI + off) = __float2bfloat16(v);
        *(__nv_bfloat16*)(smem + OFF_W2LO + off) = __float2bfloat16(v - bf16_round(v));
    }
    for (int i = tid; i < H2C * LAT; i += 256) {          // W3 [k=128][n=256]
        int k = i >> 8, n = i & 255;
        float v = W3[i];
        unsigned off = (unsigned)((k >> 6) * 32768) + (unsigned)(n * 128)
                     + ((((unsigned)(k & 63)) * 2) ^ ((n & 7) << 4));
        *(__nv_bfloat16*)(smem + OFF_W3HI + off) = __float2bfloat16(v);
        *(__nv_bfloat16*)(smem + OFF_W3LO + off) = __float2bfloat16(v - bf16_round(v));
    }
    for (int i = tid; i < 4 * H1C; i += 256) W1s[i] = W1[i];
    for (int i = tid; i < H1C;     i += 256) b1s[i] = b1[i];
    for (int i = tid; i < H2C;     i += 256) b2s[i] = b2[i];
    for (int i = tid; i < LAT;     i += 256) b3s[i] = b3[i];
    __syncthreads();

    // per-lane ldmatrix geometry
    const int lane7 = lane & 7;
    const int gA_r = ((lane >> 3) & 1) * 8 + lane7;   // A: row offset in 16x16
    const int gA_c = ((lane >> 4) & 1) * 8;           // A: col offset
    const int gB_r = ((lane >> 4) & 1) * 8 + lane7;   // B: n offset
    const int gB_c = ((lane >> 3) & 1) * 8;           // B: k offset
    const unsigned xmA = (unsigned)lane7 << 4;        // swizzle mask (row&7)<<4
    const int rq = lane >> 2;                         // c-frag row-in-8
    const int cq = 2 * (lane & 3);                    // c-frag col pair

    for (;;) {
        __syncthreads();
        if (tid == 0) *(volatile int*)(smem + OFF_TILE) = atomicAdd(&g_tile, 1);
        __syncthreads();
        const int t = *(volatile int*)(smem + OFF_TILE);
        if (t >= NT) break;
        const int P0 = t * TILE;

        // ---- feats + segs
        for (int i = tid; i < TILE * 5; i += 256) {
            int p = i / 5, c = i - p * 5;
            float v = pc[(size_t)(P0 + p) * 5 + c];
            if (c) feats[p * 4 + ((c == 4) ? 0 : c)] = v;
        }
        if (tid < TILE) segs[tid] = is64 ? seg[2 * (P0 + tid)] : seg[P0 + tid];
        __syncthreads();

        // ---- layer 1 (FFMA, K=4) -> h1 bf16 hi/lo, swizzled
        {
            int p = tid >> 2, q = tid & 3;
            float f0 = feats[p * 4 + 0], f1 = feats[p * 4 + 1];
            float f2 = feats[p * 4 + 2], f3 = feats[p * 4 + 3];
            unsigned rowb = (unsigned)(p * 128), xm = (unsigned)(p & 7) << 4;
            #pragma unroll
            for (int jj = 0; jj < 8; jj++) {
                int n = q * 16 + 2 * jj;
                float v0 = b1s[n];
                v0 = fmaf(f0, W1s[n], v0);       v0 = fmaf(f1, W1s[64 + n], v0);
                v0 = fmaf(f2, W1s[128 + n], v0); v0 = fmaf(f3, W1s[192 + n], v0);
                float v1 = b1s[n + 1];
                v1 = fmaf(f0, W1s[n + 1], v1);       v1 = fmaf(f1, W1s[65 + n], v1);
                v1 = fmaf(f2, W1s[129 + n], v1);     v1 = fmaf(f3, W1s[193 + n], v1);
                v0 = fmaxf(v0, 0.f); v1 = fmaxf(v1, 0.f);
                unsigned off = rowb + (((unsigned)(n * 2)) ^ xm);
                *(unsigned*)(smem + OFF_H1HI + off) = pack_bf16(v0, v1);
                *(unsigned*)(smem + OFF_H1LO + off) =
                    pack_bf16(v0 - bf16_round(v0), v1 - bf16_round(v1));
            }
        }
        __syncthreads();

        // ---- layer 2: C2(64x128) = h1(64x64) @ W2, 3-pass split bf16
        float acc[4][2][4];
        #pragma unroll
        for (int i = 0; i < 4; i++)
            #pragma unroll
            for (int j = 0; j < 2; j++)
                #pragma unroll
                for (int q = 0; q < 4; q++) acc[i][j][q] = 0.f;
        const int n0_2 = w * 16;
        #pragma unroll
        for (int kt = 0; kt < 4; kt++) {
            const int k0 = kt * 16;
            uint32_t Bh[4], Bl[4], Ah[4][4], Al[4][4];
            {
                unsigned boff = (unsigned)((n0_2 + gB_r) * 128)
                              + (((unsigned)((k0 + gB_c) * 2)) ^ xmA);
                ldsm4(Bh, sb + OFF_W2HI + boff);
                ldsm4(Bl, sb + OFF_W2LO + boff);
            }
            #pragma unroll
            for (int i = 0; i < 4; i++) {
                unsigned aoff = (unsigned)((i * 16 + gA_r) * 128)
                              + (((unsigned)((k0 + gA_c) * 2)) ^ xmA);
                ldsm4(Ah[i], sb + OFF_H1HI + aoff);
                ldsm4(Al[i], sb + OFF_H1LO + aoff);
            }
            #pragma unroll
            for (int i = 0; i < 4; i++) {
                mma16816(acc[i][0], Ah[i], Bh[0], Bh[1]);
                mma16816(acc[i][1], Ah[i], Bh[2], Bh[3]);
                mma16816(acc[i][0], Ah[i], Bl[0], Bl[1]);
                mma16816(acc[i][1], Ah[i], Bl[2], Bl[3]);
                mma16816(acc[i][0], Al[i], Bh[0], Bh[1]);
                mma16816(acc[i][1], Al[i], Bh[2], Bh[3]);
            }
        }

        // ---- layer-2 epilogue: bias+relu -> h2 bf16 hi/lo (n becomes k)
        #pragma unroll
        for (int i = 0; i < 4; i++)
            #pragma unroll
            for (int j = 0; j < 2; j++) {
                int n = n0_2 + j * 8 + cq;
                float v0 = fmaxf(acc[i][j][0] + b2s[n],     0.f);
                float v1 = fmaxf(acc[i][j][1] + b2s[n + 1], 0.f);
                float v2 = fmaxf(acc[i][j][2] + b2s[n],     0.f);
                float v3 = fmaxf(acc[i][j][3] + b2s[n + 1], 0.f);
                unsigned blk = (unsigned)((n >> 6) * 8192);
                int r0 = i * 16 + rq;
                unsigned cbyte = ((unsigned)((n & 63) * 2)) ^ ((unsigned)(rq & 7) << 4);
                unsigned o0 = blk + (unsigned)(r0 * 128) + cbyte;
                unsigned o1 = blk + (unsigned)((r0 + 8) * 128) + cbyte;
                *(unsigned*)(smem + OFF_H2HI + o0) = pack_bf16(v0, v1);
                *(unsigned*)(smem + OFF_H2HI + o1) = pack_bf16(v2, v3);
                *(unsigned*)(smem + OFF_H2LO + o0) =
                    pack_bf16(v0 - bf16_round(v0), v1 - bf16_round(v1));
                *(unsigned*)(smem + OFF_H2LO + o1) =
                    pack_bf16(v2 - bf16_round(v2), v3 - bf16_round(v3));
            }
        __syncthreads();

        // ---- layer 3 in two N-halves: C3(64x128) = h2(64x128) @ W3half
        const bool t_uni = (segs[0] == segs[TILE - 1]);
        #pragma unroll
        for (int half = 0; half < 2; half++) {
            const int n0 = half * 128 + w * 16;
            #pragma unroll
            for (int i = 0; i < 4; i++)
                #pragma unroll
                for (int j = 0; j < 2; j++)
                    #pragma unroll
                    for (int q = 0; q < 4; q++) acc[i][j][q] = 0.f;
            #pragma unroll
            for (int kt = 0; kt < 8; kt++) {
                const int k0 = kt * 16;
                const unsigned kblkA = (unsigned)((k0 >> 6) * 8192);
                const unsigned kblkB = (unsigned)((k0 >> 6) * 32768);
                uint32_t Bh[4], Bl[4], Ah[4][4], Al[4][4];
                {
                    unsigned boff = kblkB + (unsigned)((n0 + gB_r) * 128)
                                  + (((unsigned)(((k0 + gB_c) & 63) * 2)) ^ xmA);
                    ldsm4(Bh, sb + OFF_W3HI + boff);
                    ldsm4(Bl, sb + OFF_W3LO + boff);
                }
                #pragma unroll
                for (int i = 0; i < 4; i++) {
                    unsigned aoff = kblkA + (unsigned)((i * 16 + gA_r) * 128)
                                  + (((unsigned)(((k0 + gA_c) & 63) * 2)) ^ xmA);
                    ldsm4(Ah[i], sb + OFF_H2HI + aoff);
                    ldsm4(Al[i], sb + OFF_H2LO + aoff);
                }
                #pragma unroll
                for (int i = 0; i < 4; i++) {
                    mma16816(acc[i][0], Ah[i], Bh[0], Bh[1]);
                    mma16816(acc[i][1], Ah[i], Bh[2], Bh[3]);
                    mma16816(acc[i][0], Ah[i], Bl[0], Bl[1]);
                    mma16816(acc[i][1], Ah[i], Bl[2], Bl[3]);
                    mma16816(acc[i][0], Al[i], Bh[0], Bh[1]);
                    mma16816(acc[i][1], Al[i], Bh[2], Bh[3]);
                }
            }

            // ---- segment-max pooling epilogue
            if (t_uni) {
                const int s0 = segs[0];
                #pragma unroll
                for (int j = 0; j < 2; j++) {
                    float v0 = -3.402823466e38f, v1 = -3.402823466e38f;
                    #pragma unroll
                    for (int i = 0; i < 4; i++) {
                        v0 = fmaxf(v0, fmaxf(acc[i][j][0], acc[i][j][2]));
                        v1 = fmaxf(v1, fmaxf(acc[i][j][1], acc[i][j][3]));
                    }
                    #pragma unroll
                    for (int o = 4; o < 32; o <<= 1) {
                        v0 = fmaxf(v0, __shfl_xor_sync(0xffffffffu, v0, o));
                        v1 = fmaxf(v1, __shfl_xor_sync(0xffffffffu, v1, o));
                    }
                    if (lane < 4) {
                        int n = n0 + j * 8 + cq;
                        atomicMax(&g_pooled[s0 * LAT + n],     encf(v0 + b3s[n]));
                        atomicMax(&g_pooled[s0 * LAT + n + 1], encf(v1 + b3s[n + 1]));
                    }
                }
            } else {
                #pragma unroll
                for (int i = 0; i < 4; i++) {
                    int r0 = i * 16 + rq;
                    int sa = segs[r0], sbg = segs[r0 + 8];
                    #pragma unroll
                    for (int j = 0; j < 2; j++) {
                        int n = n0 + j * 8 + cq;
                        atomicMax(&g_pooled[sa  * LAT + n],     encf(acc[i][j][0] + b3s[n]));
                        atomicMax(&g_pooled[sa  * LAT + n + 1], encf(acc[i][j][1] + b3s[n + 1]));
                        atomicMax(&g_pooled[sbg * LAT + n],     encf(acc[i][j][2] + b3s[n]));
                        atomicMax(&g_pooled[sbg * LAT + n + 1], encf(acc[i][j][3] + b3s[n + 1]));
                    }
                }
            }
        }
    }
}

__global__ void k_final(const float* __restrict__ Wf,
                        const float* __restrict__ bf,
                        float* __restrict__ out) {
    int g = blockIdx.x, l = threadIdx.x;
    float a0 = 0.f, a1 = 0.f, a2 = 0.f;
    for (int j = l; j < LAT; j += 32) {
        float v = decf(g_pooled[g * LAT + j]);
        a0 = fmaf(v, Wf[j * 3 + 0], a0);
        a1 = fmaf(v, Wf[j * 3 + 1], a1);
        a2 = fmaf(v, Wf[j * 3 + 2], a2);
    }
    #pragma unroll
    for (int o = 16; o > 0; o >>= 1) {
        a0 += __shfl_down_sync(0xffffffffu, a0, o);
        a1 += __shfl_down_sync(0xffffffffu, a1, o);
        a2 += __shfl_down_sync(0xffffffffu, a2, o);
    }
    if (l == 0) {
        float inv = 1.f / fmaxf(g_cnt[g], 1.f);
        out[g * 3 + 0] = g_csum[g * 3 + 0] * inv + softplus_f(a0 + bf[0]);
        out[g * 3 + 1] = g_csum[g * 3 + 1] * inv + softplus_f(a1 + bf[1]);
        out[g * 3 + 2] = g_csum[g * 3 + 2] * inv + softplus_f(a2 + bf[2]);
    }
}

// ---------------- launch --------------------------------------------------
extern "C" void kernel_launch(void* const* d_in, const int* in_sizes, int n_in,
                              void* d_out, int out_size) {
    const float* pc = (const float*)d_in[0];
    const float* W1 = (const float*)d_in[1];
    const float* b1 = (const float*)d_in[2];
    const float* W2 = (const float*)d_in[3];
    const float* b2 = (const float*)d_in[4];
    const float* W3 = (const float*)d_in[5];
    const float* b3 = (const float*)d_in[6];
    const float* Wf = (const float*)d_in[7];
    const float* bf = (const float*)d_in[8];
    const int*   sg = (const int*)d_in[9];
    float* out = (float*)d_out;
    (void)in_sizes; (void)n_in; (void)out_size;

    cudaFuncSetAttribute(k_mlp, cudaFuncAttributeMaxDynamicSharedMemorySize,
                         SMEM_TOTAL);
    int sms = 148;
    cudaDeviceGetAttribute(&sms, cudaDevAttrMultiProcessorCount, 0);

    k_init<<<64, 256>>>();
    k_centroid<<<3125, 320>>>(pc, sg);
    k_mlp<<<sms, 256, SMEM_TOTAL>>>(pc, W1, b1, W2, b2, W3, b3, sg);
    k_final<<<G, 32>>>(Wf, bf, out);
}

// round 4
// speedup vs baseline: 3.8811x; 1.3931x over previous
#include <cuda_runtime.h>
#include <cuda_fp16.h>
#include <cstdint>
#include <math.h>

#define N_PTS 1000000
#define G     256
#define H1C   64
#define H2C   128
#define LAT   256
#define TILE  64
#define NT    15625         // 1e6 / 64 exactly

// ---------------- scratch -----------------------------------------------
__device__ unsigned g_pooled[G * LAT];
__device__ float    g_csum[G * 3];
__device__ float    g_cnt[G];

__device__ __forceinline__ unsigned encf(float f) {
    unsigned u = __float_as_uint(f);
    return (u & 0x80000000u) ? ~u : (u | 0x80000000u);
}
__device__ __forceinline__ float decf(unsigned u) {
    return (u & 0x80000000u) ? __uint_as_float(u ^ 0x80000000u)
                             : __uint_as_float(~u);
}
__device__ __forceinline__ float softplus_f(float x) {
    return fmaxf(x, 0.f) + log1pf(expf(-fabsf(x)));
}

// ---------------- mma.sync helpers --------------------------------------
__device__ __forceinline__ uint32_t smem_u32(const void* p) {
    uint32_t a;
    asm("{ .reg .u64 t; cvta.to.shared.u64 t, %1; cvt.u32.u64 %0, t; }"
        : "=r"(a) : "l"(p));
    return a;
}
__device__ __forceinline__ void ldsm4(uint32_t r[4], uint32_t a) {
    asm volatile("ldmatrix.sync.aligned.m8n8.x4.shared.b16 {%0,%1,%2,%3}, [%4];"
        : "=r"(r[0]), "=r"(r[1]), "=r"(r[2]), "=r"(r[3]) : "r"(a));
}
__device__ __forceinline__ void mma16816(float d[4], const uint32_t a[4],
                                         uint32_t b0, uint32_t b1) {
    asm volatile(
        "mma.sync.aligned.m16n8k16.row.col.f32.f16.f16.f32 "
        "{%0,%1,%2,%3}, {%4,%5,%6,%7}, {%8,%9}, {%0,%1,%2,%3};"
        : "+f"(d[0]), "+f"(d[1]), "+f"(d[2]), "+f"(d[3])
        : "r"(a[0]), "r"(a[1]), "r"(a[2]), "r"(a[3]), "r"(b0), "r"(b1));
}
__device__ __forceinline__ unsigned pack_f16(float lo, float hi) {
    unsigned r;
    asm("cvt.rn.f16x2.f32 %0, %1, %2;" : "=r"(r) : "f"(hi), "f"(lo));
    return r;  // low 16 bits = lo
}

// ---------------- SMEM layout (bytes; tiles 1024-aligned) ----------------
// Weight tiles [n][k] fp16, 128B rows (64 k per block), SW128 swizzle.
#define OFF_W3HI  0         // 2 kblk x 256 x 128B = 65536
#define OFF_W3LO  65536
#define OFF_W2HI  131072    // 128 x 128B = 16384
#define OFF_W2LO  147456
#define OFF_H1    163840    // 64 x 128B = 8192
#define OFF_H2    172032    // 2 kblk x 64 x 128B = 16384
#define OFF_FEATS 188416    // 64*4 f
#define OFF_W1    189440    // 256 f
#define OFF_B1    190464
#define OFF_B2    190720
#define OFF_B3    191232
#define OFF_SEGS  192256    // 2 x 64 ints (double buffered)
#define SMEM_TOTAL 193024

// ---------------- kernels ------------------------------------------------
__global__ void k_init() {
    int i = blockIdx.x * blockDim.x + threadIdx.x;
    int stride = gridDim.x * blockDim.x;
    for (int j = i; j < G * LAT; j += stride) g_pooled[j] = 0u;
    if (i < G * 3) g_csum[i] = 0.f;
    if (i < G)     g_cnt[i]  = 0.f;
}

__global__ void k_centroid(const float* __restrict__ pc,
                           const int*   __restrict__ seg) {
    const bool is64 = (seg[N_PTS - 1] == 0);
    int p = blockIdx.x * blockDim.x + threadIdx.x;
    float x = pc[(size_t)p * 5 + 1];
    float y = pc[(size_t)p * 5 + 2];
    float z = pc[(size_t)p * 5 + 3];
    int s = is64 ? seg[2 * p] : seg[p];
    int s0 = __shfl_sync(0xffffffffu, s, 0);
    if (__all_sync(0xffffffffu, s == s0)) {
        #pragma unroll
        for (int o = 16; o > 0; o >>= 1) {
            x += __shfl_down_sync(0xffffffffu, x, o);
            y += __shfl_down_sync(0xffffffffu, y, o);
            z += __shfl_down_sync(0xffffffffu, z, o);
        }
        if ((threadIdx.x & 31) == 0) {
            atomicAdd(&g_csum[s * 3 + 0], x);
            atomicAdd(&g_csum[s * 3 + 1], y);
            atomicAdd(&g_csum[s * 3 + 2], z);
            atomicAdd(&g_cnt[s], 32.f);
        }
    } else {
        atomicAdd(&g_csum[s * 3 + 0], x);
        atomicAdd(&g_csum[s * 3 + 1], y);
        atomicAdd(&g_csum[s * 3 + 2], z);
        atomicAdd(&g_cnt[s], 1.f);
    }
}

__global__ __launch_bounds__(256, 1)
void k_mlp(const float* __restrict__ pc,
           const float* __restrict__ W1, const float* __restrict__ b1,
           const float* __restrict__ W2, const float* __restrict__ b2,
           const float* __restrict__ W3, const float* __restrict__ b3,
           const int*   __restrict__ seg) {
    extern __shared__ __align__(1024) char smem[];
    const uint32_t sb = smem_u32(smem);
    const int tid  = threadIdx.x;
    const int w    = tid >> 5;
    const int lane = tid & 31;
    const bool is64 = (seg[N_PTS - 1] == 0);

    float* feats = (float*)(smem + OFF_FEATS);
    float* W1s   = (float*)(smem + OFF_W1);
    float* b1s   = (float*)(smem + OFF_B1);
    float* b2s   = (float*)(smem + OFF_B2);
    float* b3s   = (float*)(smem + OFF_B3);
    int*   segsA = (int*)  (smem + OFF_SEGS);
    int*   segsB = segsA + 64;

    // ---- one-time weight prep: transpose to [n][k], fp16 hi/lo, SW128 ----
    for (int i = tid; i < H1C * H2C; i += 256) {          // W2 [k=64][n=128]
        int k = i >> 7, n = i & 127;
        float v = W2[i];
        __half h = __float2half_rn(v);
        unsigned off = (unsigned)(n * 128) + (((unsigned)(k * 2)) ^ ((n & 7) << 4));
        *(__half*)(smem + OFF_W2HI + off) = h;
        *(__half*)(smem + OFF_W2LO + off) = __float2half_rn(v - __half2float(h));
    }
    for (int i = tid; i < H2C * LAT; i += 256) {          // W3 [k=128][n=256]
        int k = i >> 8, n = i & 255;
        float v = W3[i];
        __half h = __float2half_rn(v);
        unsigned off = (unsigned)((k >> 6) * 32768) + (unsigned)(n * 128)
                     + ((((unsigned)(k & 63)) * 2) ^ ((n & 7) << 4));
        *(__half*)(smem + OFF_W3HI + off) = h;
        *(__half*)(smem + OFF_W3LO + off) = __float2half_rn(v - __half2float(h));
    }
    for (int i = tid; i < 4 * H1C; i += 256) W1s[i] = W1[i];
    for (int i = tid; i < H1C;     i += 256) b1s[i] = b1[i];
    for (int i = tid; i < H2C;     i += 256) b2s[i] = b2[i];
    for (int i = tid; i < LAT;     i += 256) b3s[i] = b3[i];

    // per-lane ldmatrix geometry (same as validated round-3 layout)
    const int lane7 = lane & 7;
    const int gA_r = ((lane >> 3) & 1) * 8 + lane7;   // A row offset in 16x16
    const int gA_c = ((lane >> 4) & 1) * 8;           // A col offset
    const int gB_r = ((lane >> 4) & 1) * 8 + lane7;   // B n offset
    const int gB_c = ((lane >> 3) & 1) * 8;           // B k offset
    const unsigned xmA = (unsigned)lane7 << 4;        // swizzle (row&7)<<4
    const int rq = lane >> 2;                         // c-frag row-in-8
    const int cq = 2 * (lane & 3);                    // c-frag col pair

    int it = 0;
    for (int t = blockIdx.x; t < NT; t += gridDim.x, it++) {
        const int P0 = t * TILE;
        int* segs = (it & 1) ? segsB : segsA;

        // ---- feats + segs (segs double-buffered: prev epilogue may lag)
        for (int i = tid; i < TILE * 5; i += 256) {
            int p = i / 5, c = i - p * 5;
            float v = pc[(size_t)(P0 + p) * 5 + c];
            if (c) feats[p * 4 + ((c == 4) ? 0 : c)] = v;
        }
        if (tid < TILE) segs[tid] = is64 ? seg[2 * (P0 + tid)] : seg[P0 + tid];
        __syncthreads();                     // sync1: feats/segs ready

        // ---- layer 1 (FFMA, K=4) -> h1 fp16, swizzled
        {
            int p = tid >> 2, q = tid & 3;
            float f0 = feats[p * 4 + 0], f1 = feats[p * 4 + 1];
            float f2 = feats[p * 4 + 2], f3 = feats[p * 4 + 3];
            unsigned rowb = (unsigned)(p * 128), xm = (unsigned)(p & 7) << 4;
            #pragma unroll
            for (int jj = 0; jj < 8; jj++) {
                int n = q * 16 + 2 * jj;
                float v0 = b1s[n];
                v0 = fmaf(f0, W1s[n], v0);       v0 = fmaf(f1, W1s[64 + n], v0);
                v0 = fmaf(f2, W1s[128 + n], v0); v0 = fmaf(f3, W1s[192 + n], v0);
                float v1 = b1s[n + 1];
                v1 = fmaf(f0, W1s[n + 1], v1);       v1 = fmaf(f1, W1s[65 + n], v1);
                v1 = fmaf(f2, W1s[129 + n], v1);     v1 = fmaf(f3, W1s[193 + n], v1);
                v0 = fmaxf(v0, 0.f); v1 = fmaxf(v1, 0.f);
                unsigned off = rowb + (((unsigned)(n * 2)) ^ xm);
                *(unsigned*)(smem + OFF_H1 + off) = pack_f16(v0, v1);
            }
        }
        __syncthreads();                     // sync2: h1 ready

        // ---- layer 2: C2(64x128) = h1 @ (W2hi + W2lo), warp n-slice 16
        {
            float acc[4][2][4];
            #pragma unroll
            for (int i = 0; i < 4; i++)
                #pragma unroll
                for (int j = 0; j < 2; j++)
                    #pragma unroll
                    for (int q = 0; q < 4; q++) acc[i][j][q] = 0.f;
            const int n0 = w * 16;
            #pragma unroll
            for (int kt = 0; kt < 4; kt++) {
                const int k0 = kt * 16;
                uint32_t Bh[4], Bl[4];
                unsigned boff = (unsigned)((n0 + gB_r) * 128)
                              + (((unsigned)((k0 + gB_c) * 2)) ^ xmA);
                ldsm4(Bh, sb + OFF_W2HI + boff);
                ldsm4(Bl, sb + OFF_W2LO + boff);
                #pragma unroll
                for (int i = 0; i < 4; i++) {
                    uint32_t Ah[4];
                    unsigned aoff = (unsigned)((i * 16 + gA_r) * 128)
                                  + (((unsigned)((k0 + gA_c) * 2)) ^ xmA);
                    ldsm4(Ah, sb + OFF_H1 + aoff);
                    mma16816(acc[i][0], Ah, Bh[0], Bh[1]);
                    mma16816(acc[i][1], Ah, Bh[2], Bh[3]);
                    mma16816(acc[i][0], Ah, Bl[0], Bl[1]);
                    mma16816(acc[i][1], Ah, Bl[2], Bl[3]);
                }
            }
            // epilogue: bias+relu -> h2 fp16 (n becomes k)
            #pragma unroll
            for (int i = 0; i < 4; i++)
                #pragma unroll
                for (int j = 0; j < 2; j++) {
                    int n = n0 + j * 8 + cq;
                    float v0 = fmaxf(acc[i][j][0] + b2s[n],     0.f);
                    float v1 = fmaxf(acc[i][j][1] + b2s[n + 1], 0.f);
                    float v2 = fmaxf(acc[i][j][2] + b2s[n],     0.f);
                    float v3 = fmaxf(acc[i][j][3] + b2s[n + 1], 0.f);
                    unsigned blk = (unsigned)((n >> 6) * 8192);
                    int r0 = i * 16 + rq;
                    unsigned cbyte = ((unsigned)((n & 63) * 2))
                                   ^ ((unsigned)(rq & 7) << 4);
                    *(unsigned*)(smem + OFF_H2 + blk + (unsigned)(r0 * 128) + cbyte)
                        = pack_f16(v0, v1);
                    *(unsigned*)(smem + OFF_H2 + blk + (unsigned)((r0 + 8) * 128) + cbyte)
                        = pack_f16(v2, v3);
                }
        }
        __syncthreads();                     // sync3: h2 ready

        // ---- layer 3: C3(64x256) = h2 @ (W3hi + W3lo), warp n-slice 32
        float acc3[4][4][4];
        #pragma unroll
        for (int i = 0; i < 4; i++)
            #pragma unroll
            for (int j = 0; j < 4; j++)
                #pragma unroll
                for (int q = 0; q < 4; q++) acc3[i][j][q] = 0.f;
        const int n0 = w * 32;
        #pragma unroll
        for (int kt = 0; kt < 8; kt++) {
            const int k0 = kt * 16;
            const unsigned kbA = (unsigned)((k0 >> 6) * 8192);
            const unsigned kbB = (unsigned)((k0 >> 6) * 32768);
            const unsigned kby = ((unsigned)(((k0 & 63) + gB_c) * 2)) ^ xmA;
            uint32_t Bh[2][4], Bl[2][4];
            #pragma unroll
            for (int nb = 0; nb < 2; nb++) {
                unsigned boff = kbB + (unsigned)((n0 + nb * 16 + gB_r) * 128) + kby;
                ldsm4(Bh[nb], sb + OFF_W3HI + boff);
                ldsm4(Bl[nb], sb + OFF_W3LO + boff);
            }
            const unsigned kay = ((unsigned)(((k0 & 63) + gA_c) * 2)) ^ xmA;
            #pragma unroll
            for (int i = 0; i < 4; i++) {
                uint32_t Ah[4];
                ldsm4(Ah, sb + OFF_H2 + kbA + (unsigned)((i * 16 + gA_r) * 128) + kay);
                #pragma unroll
                for (int nb = 0; nb < 2; nb++) {
                    mma16816(acc3[i][2 * nb + 0], Ah, Bh[nb][0], Bh[nb][1]);
                    mma16816(acc3[i][2 * nb + 1], Ah, Bh[nb][2], Bh[nb][3]);
                    mma16816(acc3[i][2 * nb + 0], Ah, Bl[nb][0], Bl[nb][1]);
                    mma16816(acc3[i][2 * nb + 1], Ah, Bl[nb][2], Bl[nb][3]);
                }
            }
        }

        // ---- segment-max pooling epilogue
        if (segs[0] == segs[TILE - 1]) {
            const int s0 = segs[0];
            #pragma unroll
            for (int j = 0; j < 4; j++) {
                float v0 = -3.402823466e38f, v1 = -3.402823466e38f;
                #pragma unroll
                for (int i = 0; i < 4; i++) {
                    v0 = fmaxf(v0, fmaxf(acc3[i][j][0], acc3[i][j][2]));
                    v1 = fmaxf(v1, fmaxf(acc3[i][j][1], acc3[i][j][3]));
                }
                #pragma unroll
                for (int o = 4; o < 32; o <<= 1) {
                    v0 = fmaxf(v0, __shfl_xor_sync(0xffffffffu, v0, o));
                    v1 = fmaxf(v1, __shfl_xor_sync(0xffffffffu, v1, o));
                }
                if (lane < 4) {
                    int n = n0 + j * 8 + cq;
                    atomicMax(&g_pooled[s0 * LAT + n],     encf(v0 + b3s[n]));
                    atomicMax(&g_pooled[s0 * LAT + n + 1], encf(v1 + b3s[n + 1]));
                }
            }
        } else {
            #pragma unroll
            for (int i = 0; i < 4; i++) {
                int r0 = i * 16 + rq;
                int sa = segs[r0], sbg = segs[r0 + 8];
                #pragma unroll
                for (int j = 0; j < 4; j++) {
                    int n = n0 + j * 8 + cq;
                    atomicMax(&g_pooled[sa  * LAT + n],     encf(acc3[i][j][0] + b3s[n]));
                    atomicMax(&g_pooled[sa  * LAT + n + 1], encf(acc3[i][j][1] + b3s[n + 1]));
                    atomicMax(&g_pooled[sbg * LAT + n],     encf(acc3[i][j][2] + b3s[n]));
                    atomicMax(&g_pooled[sbg * LAT + n + 1], encf(acc3[i][j][3] + b3s[n + 1]));
                }
            }
        }
    }
}

__global__ void k_final(const float* __restrict__ Wf,
                        const float* __restrict__ bf,
                        float* __restrict__ out) {
    int g = blockIdx.x, l = threadIdx.x;
    float a0 = 0.f, a1 = 0.f, a2 = 0.f;
    for (int j = l; j < LAT; j += 32) {
        float v = decf(g_pooled[g * LAT + j]);
        a0 = fmaf(v, Wf[j * 3 + 0], a0);
        a1 = fmaf(v, Wf[j * 3 + 1], a1);
        a2 = fmaf(v, Wf[j * 3 + 2], a2);
    }
    #pragma unroll
    for (int o = 16; o > 0; o >>= 1) {
        a0 += __shfl_down_sync(0xffffffffu, a0, o);
        a1 += __shfl_down_sync(0xffffffffu, a1, o);
        a2 += __shfl_down_sync(0xffffffffu, a2, o);
    }
    if (l == 0) {
        float inv = 1.f / fmaxf(g_cnt[g], 1.f);
        out[g * 3 + 0] = g_csum[g * 3 + 0] * inv + softplus_f(a0 + bf[0]);
        out[g * 3 + 1] = g_csum[g * 3 + 1] * inv + softplus_f(a1 + bf[1]);
        out[g * 3 + 2] = g_csum[g * 3 + 2] * inv + softplus_f(a2 + bf[2]);
    }
}

// ---------------- launch --------------------------------------------------
extern "C" void kernel_launch(void* const* d_in, const int* in_sizes, int n_in,
                              void* d_out, int out_size) {
    const float* pc = (const float*)d_in[0];
    const float* W1 = (const float*)d_in[1];
    const float* b1 = (const float*)d_in[2];
    const float* W2 = (const float*)d_in[3];
    const float* b2 = (const float*)d_in[4];
    const float* W3 = (const float*)d_in[5];
    const float* b3 = (const float*)d_in[6];
    const float* Wf = (const float*)d_in[7];
    const float* bf = (const float*)d_in[8];
    const int*   sg = (const int*)d_in[9];
    float* out = (float*)d_out;
    (void)in_sizes; (void)n_in; (void)out_size;

    cudaFuncSetAttribute(k_mlp, cudaFuncAttributeMaxDynamicSharedMemorySize,
                         SMEM_TOTAL);
    int sms = 148;
    cudaDeviceGetAttribute(&sms, cudaDevAttrMultiProcessorCount, 0);

    k_init<<<64, 256>>>();
    k_centroid<<<3125, 320>>>(pc, sg);
    k_mlp<<<sms, 256, SMEM_TOTAL>>>(pc, W1, b1, W2, b2, W3, b3, sg);
    k_final<<<G, 32>>>(Wf, bf, out);
}

// round 5
// speedup vs baseline: 6.6677x; 1.7180x over previous
#include <cuda_runtime.h>
#include <cuda_fp16.h>
#include <cstdint>
#include <math.h>

#define N_PTS 1000000
#define G     256
#define H1C   64
#define H2C   128
#define LAT   256
#define TILE  128
#define NT    7813          // ceil(1e6/128)

// ---------------- scratch -----------------------------------------------
__device__ unsigned g_pooled[G * LAT];
__device__ float    g_csum[G * 3];
__device__ float    g_cnt[G];

__device__ __forceinline__ unsigned encf(float f) {
    unsigned u = __float_as_uint(f);
    return (u & 0x80000000u) ? ~u : (u | 0x80000000u);
}
__device__ __forceinline__ float decf(unsigned u) {
    return (u & 0x80000000u) ? __uint_as_float(u ^ 0x80000000u)
                             : __uint_as_float(~u);
}
__device__ __forceinline__ float softplus_f(float x) {
    return fmaxf(x, 0.f) + log1pf(expf(-fabsf(x)));
}

// ---------------- mma.sync helpers --------------------------------------
__device__ __forceinline__ uint32_t smem_u32(const void* p) {
    uint32_t a;
    asm("{ .reg .u64 t; cvta.to.shared.u64 t, %1; cvt.u32.u64 %0, t; }"
        : "=r"(a) : "l"(p));
    return a;
}
__device__ __forceinline__ void ldsm4(uint32_t r[4], uint32_t a) {
    asm volatile("ldmatrix.sync.aligned.m8n8.x4.shared.b16 {%0,%1,%2,%3}, [%4];"
        : "=r"(r[0]), "=r"(r[1]), "=r"(r[2]), "=r"(r[3]) : "r"(a));
}
__device__ __forceinline__ void mma16816(float d[4], const uint32_t a[4],
                                         uint32_t b0, uint32_t b1) {
    asm volatile(
        "mma.sync.aligned.m16n8k16.row.col.f32.f16.f16.f32 "
        "{%0,%1,%2,%3}, {%4,%5,%6,%7}, {%8,%9}, {%0,%1,%2,%3};"
        : "+f"(d[0]), "+f"(d[1]), "+f"(d[2]), "+f"(d[3])
        : "r"(a[0]), "r"(a[1]), "r"(a[2]), "r"(a[3]), "r"(b0), "r"(b1));
}
__device__ __forceinline__ unsigned pack_f16(float lo, float hi) {
    unsigned r;
    asm("cvt.rn.f16x2.f32 %0, %1, %2;" : "=r"(r) : "f"(hi), "f"(lo));
    return r;  // low 16 bits = lo
}

// ---------------- SMEM layout (bytes; tiles 1024-aligned) ----------------
// Weight tiles [n][k] fp16, 128B rows (64 k per block), SW128 swizzle.
#define OFF_W3    0         // 2 kblk x 256 x 128B = 65536
#define OFF_W2    65536     // 128 x 128B = 16384
#define OFF_H1    81920     // 128 x 128B = 16384
#define OFF_H2    98304     // 2 kblk x 128 x 128B = 32768
#define OFF_FEATS 131072    // 128*4 f = 2048
#define OFF_W1    133120    // 256 f
#define OFF_B1    134144
#define OFF_B2    134400
#define OFF_B3    134912
#define OFF_SEGS  135936    // 2 x 128 ints (double buffered)
#define SMEM_TOTAL 137216

// ---------------- kernels ------------------------------------------------
__global__ void k_init() {
    int i = blockIdx.x * blockDim.x + threadIdx.x;
    int stride = gridDim.x * blockDim.x;
    for (int j = i; j < G * LAT; j += stride) g_pooled[j] = 0u;
    if (i < G * 3) g_csum[i] = 0.f;
    if (i < G)     g_cnt[i]  = 0.f;
}

__global__ __launch_bounds__(256, 1)
void k_mlp(const float* __restrict__ pc,
           const float* __restrict__ W1, const float* __restrict__ b1,
           const float* __restrict__ W2, const float* __restrict__ b2,
           const float* __restrict__ W3, const float* __restrict__ b3,
           const int*   __restrict__ seg) {
    extern __shared__ __align__(1024) char smem[];
    const uint32_t sb = smem_u32(smem);
    const int tid  = threadIdx.x;
    const int w    = tid >> 5;
    const int lane = tid & 31;
    const int mh   = w >> 2;        // M-half (rows mh*64 .. +63)
    const int ns   = w & 3;         // N-slice index
    const bool is64 = (seg[N_PTS - 1] == 0);

    float* feats = (float*)(smem + OFF_FEATS);
    float* W1s   = (float*)(smem + OFF_W1);
    float* b1s   = (float*)(smem + OFF_B1);
    float* b2s   = (float*)(smem + OFF_B2);
    float* b3s   = (float*)(smem + OFF_B3);
    int*   segsA = (int*)  (smem + OFF_SEGS);
    int*   segsB = segsA + TILE;

    // ---- one-time weight prep: transpose to [n][k] fp16, SW128 ----------
    for (int i = tid; i < H1C * H2C; i += 256) {          // W2 [k=64][n=128]
        int k = i >> 7, n = i & 127;
        unsigned off = (unsigned)(n * 128) + (((unsigned)(k * 2)) ^ ((n & 7) << 4));
        *(__half*)(smem + OFF_W2 + off) = __float2half_rn(W2[i]);
    }
    for (int i = tid; i < H2C * LAT; i += 256) {          // W3 [k=128][n=256]
        int k = i >> 8, n = i & 255;
        unsigned off = (unsigned)((k >> 6) * 32768) + (unsigned)(n * 128)
                     + ((((unsigned)(k & 63)) * 2) ^ ((n & 7) << 4));
        *(__half*)(smem + OFF_W3 + off) = __float2half_rn(W3[i]);
    }
    for (int i = tid; i < 4 * H1C; i += 256) W1s[i] = W1[i];
    for (int i = tid; i < H1C;     i += 256) b1s[i] = b1[i];
    for (int i = tid; i < H2C;     i += 256) b2s[i] = b2[i];
    for (int i = tid; i < LAT;     i += 256) b3s[i] = b3[i];

    // per-lane ldmatrix geometry (validated layout)
    const int lane7 = lane & 7;
    const int gA_r = ((lane >> 3) & 1) * 8 + lane7;   // A row offset in 16x16
    const int gA_c = ((lane >> 4) & 1) * 8;           // A col offset
    const int gB_r = ((lane >> 4) & 1) * 8 + lane7;   // B n offset
    const int gB_c = ((lane >> 3) & 1) * 8;           // B k offset
    const unsigned xmA = (unsigned)lane7 << 4;        // swizzle (row&7)<<4
    const int rq = lane >> 2;                         // c-frag row-in-8
    const int cq = 2 * (lane & 3);                    // c-frag col pair

    int it = 0;
    for (int t = blockIdx.x; t < NT; t += gridDim.x, it++) {
        const long P0 = (long)t * TILE;
        int* segs = (it & 1) ? segsB : segsA;

        // ---- tile load + fused centroid (one thread per point) ----------
        if (tid < TILE) {
            const int p = tid;
            long gp = P0 + p;
            const bool valid = (gp < N_PTS);
            if (!valid) gp = N_PTS - 1;
            float c1 = pc[gp * 5 + 1];
            float c2 = pc[gp * 5 + 2];
            float c3 = pc[gp * 5 + 3];
            float c4 = pc[gp * 5 + 4];
            feats[p * 4 + 0] = c4;
            feats[p * 4 + 1] = c1;
            feats[p * 4 + 2] = c2;
            feats[p * 4 + 3] = c3;
            int s = is64 ? seg[2 * gp] : seg[gp];
            segs[p] = s;
            // centroid contributions (each point once: static schedule)
            float x = valid ? c1 : 0.f, y = valid ? c2 : 0.f;
            float z = valid ? c3 : 0.f, cn = valid ? 1.f : 0.f;
            int s0 = __shfl_sync(0xffffffffu, s, 0);
            if (__all_sync(0xffffffffu, s == s0)) {
                #pragma unroll
                for (int o = 16; o > 0; o >>= 1) {
                    x  += __shfl_down_sync(0xffffffffu, x,  o);
                    y  += __shfl_down_sync(0xffffffffu, y,  o);
                    z  += __shfl_down_sync(0xffffffffu, z,  o);
                    cn += __shfl_down_sync(0xffffffffu, cn, o);
                }
                if (lane == 0) {
                    atomicAdd(&g_csum[s * 3 + 0], x);
                    atomicAdd(&g_csum[s * 3 + 1], y);
                    atomicAdd(&g_csum[s * 3 + 2], z);
                    atomicAdd(&g_cnt[s], cn);
                }
            } else if (valid) {
                atomicAdd(&g_csum[s * 3 + 0], x);
                atomicAdd(&g_csum[s * 3 + 1], y);
                atomicAdd(&g_csum[s * 3 + 2], z);
                atomicAdd(&g_cnt[s], 1.f);
            }
        }
        __syncthreads();                     // sync1: feats/segs ready

        // ---- layer 1 (FFMA, K=4) -> h1 fp16, swizzled (2 thr/point)
        {
            int p = tid >> 1, q = tid & 1;
            float f0 = feats[p * 4 + 0], f1 = feats[p * 4 + 1];
            float f2 = feats[p * 4 + 2], f3 = feats[p * 4 + 3];
            unsigned rowb = (unsigned)(p * 128), xm = (unsigned)(p & 7) << 4;
            #pragma unroll
            for (int jj = 0; jj < 16; jj++) {
                int n = q * 32 + 2 * jj;
                float v0 = b1s[n];
                v0 = fmaf(f0, W1s[n], v0);       v0 = fmaf(f1, W1s[64 + n], v0);
                v0 = fmaf(f2, W1s[128 + n], v0); v0 = fmaf(f3, W1s[192 + n], v0);
                float v1 = b1s[n + 1];
                v1 = fmaf(f0, W1s[n + 1], v1);       v1 = fmaf(f1, W1s[65 + n], v1);
                v1 = fmaf(f2, W1s[129 + n], v1);     v1 = fmaf(f3, W1s[193 + n], v1);
                v0 = fmaxf(v0, 0.f); v1 = fmaxf(v1, 0.f);
                unsigned off = rowb + (((unsigned)(n * 2)) ^ xm);
                *(unsigned*)(smem + OFF_H1 + off) = pack_f16(v0, v1);
            }
        }
        __syncthreads();                     // sync2: h1 ready

        // ---- layer 2: C2(128x128) = h1 @ W2; warp = (mh 64 rows, ns 32 n)
        {
            float acc[4][4][4];
            #pragma unroll
            for (int i = 0; i < 4; i++)
                #pragma unroll
                for (int j = 0; j < 4; j++)
                    #pragma unroll
                    for (int q = 0; q < 4; q++) acc[i][j][q] = 0.f;
            const int n0 = ns * 32;
            #pragma unroll
            for (int kt = 0; kt < 4; kt++) {
                const int k0 = kt * 16;
                uint32_t Bh[2][4];
                #pragma unroll
                for (int nb = 0; nb < 2; nb++) {
                    unsigned boff = (unsigned)((n0 + nb * 16 + gB_r) * 128)
                                  + (((unsigned)((k0 + gB_c) * 2)) ^ xmA);
                    ldsm4(Bh[nb], sb + OFF_W2 + boff);
                }
                #pragma unroll
                for (int i = 0; i < 4; i++) {
                    uint32_t Ah[4];
                    unsigned aoff = (unsigned)((mh * 64 + i * 16 + gA_r) * 128)
                                  + (((unsigned)((k0 + gA_c) * 2)) ^ xmA);
                    ldsm4(Ah, sb + OFF_H1 + aoff);
                    #pragma unroll
                    for (int nb = 0; nb < 2; nb++) {
                        mma16816(acc[i][2 * nb + 0], Ah, Bh[nb][0], Bh[nb][1]);
                        mma16816(acc[i][2 * nb + 1], Ah, Bh[nb][2], Bh[nb][3]);
                    }
                }
            }
            // epilogue: bias+relu -> h2 fp16 (n becomes k)
            #pragma unroll
            for (int i = 0; i < 4; i++)
                #pragma unroll
                for (int j = 0; j < 4; j++) {
                    int n = n0 + j * 8 + cq;
                    float v0 = fmaxf(acc[i][j][0] + b2s[n],     0.f);
                    float v1 = fmaxf(acc[i][j][1] + b2s[n + 1], 0.f);
                    float v2 = fmaxf(acc[i][j][2] + b2s[n],     0.f);
                    float v3 = fmaxf(acc[i][j][3] + b2s[n + 1], 0.f);
                    unsigned blk = (unsigned)((n >> 6) * 16384);
                    int r0 = mh * 64 + i * 16 + rq;
                    unsigned cbyte = ((unsigned)((n & 63) * 2))
                                   ^ ((unsigned)rq << 4);
                    *(unsigned*)(smem + OFF_H2 + blk + (unsigned)(r0 * 128) + cbyte)
                        = pack_f16(v0, v1);
                    *(unsigned*)(smem + OFF_H2 + blk + (unsigned)((r0 + 8) * 128) + cbyte)
                        = pack_f16(v2, v3);
                }
        }
        __syncthreads();                     // sync3: h2 ready

        // ---- layer 3: C3(128x256) = h2 @ W3; warp = (mh 64 rows, ns 64 n)
        float acc3[4][8][4];
        #pragma unroll
        for (int i = 0; i < 4; i++)
            #pragma unroll
            for (int j = 0; j < 8; j++)
                #pragma unroll
                for (int q = 0; q < 4; q++) acc3[i][j][q] = 0.f;
        const int n0 = ns * 64;
        #pragma unroll
        for (int kt = 0; kt < 8; kt++) {
            const int k0 = kt * 16;
            const unsigned kbA = (unsigned)((k0 >> 6) * 16384);
            const unsigned kbB = (unsigned)((k0 >> 6) * 32768);
            const unsigned kby = ((unsigned)(((k0 & 63) + gB_c) * 2)) ^ xmA;
            const unsigned kay = ((unsigned)(((k0 & 63) + gA_c) * 2)) ^ xmA;
            uint32_t Bh[4][4];
            #pragma unroll
            for (int nb = 0; nb < 4; nb++) {
                unsigned boff = kbB + (unsigned)((n0 + nb * 16 + gB_r) * 128) + kby;
                ldsm4(Bh[nb], sb + OFF_W3 + boff);
            }
            #pragma unroll
            for (int i = 0; i < 4; i++) {
                uint32_t Ah[4];
                ldsm4(Ah, sb + OFF_H2 + kbA
                      + (unsigned)((mh * 64 + i * 16 + gA_r) * 128) + kay);
                #pragma unroll
                for (int nb = 0; nb < 4; nb++) {
                    mma16816(acc3[i][2 * nb + 0], Ah, Bh[nb][0], Bh[nb][1]);
                    mma16816(acc3[i][2 * nb + 1], Ah, Bh[nb][2], Bh[nb][3]);
                }
            }
        }

        // ---- segment-max pooling epilogue
        if (segs[0] == segs[TILE - 1]) {
            const int s0 = segs[0];
            #pragma unroll
            for (int j = 0; j < 8; j++) {
                float v0 = -3.402823466e38f, v1 = -3.402823466e38f;
                #pragma unroll
                for (int i = 0; i < 4; i++) {
                    v0 = fmaxf(v0, fmaxf(acc3[i][j][0], acc3[i][j][2]));
                    v1 = fmaxf(v1, fmaxf(acc3[i][j][1], acc3[i][j][3]));
                }
                #pragma unroll
                for (int o = 4; o < 32; o <<= 1) {
                    v0 = fmaxf(v0, __shfl_xor_sync(0xffffffffu, v0, o));
                    v1 = fmaxf(v1, __shfl_xor_sync(0xffffffffu, v1, o));
                }
                if (lane < 4) {
                    int n = n0 + j * 8 + cq;
                    atomicMax(&g_pooled[s0 * LAT + n],     encf(v0 + b3s[n]));
                    atomicMax(&g_pooled[s0 * LAT + n + 1], encf(v1 + b3s[n + 1]));
                }
            }
        } else {
            #pragma unroll
            for (int i = 0; i < 4; i++) {
                int r0 = mh * 64 + i * 16 + rq;
                int sa = segs[r0], sbg = segs[r0 + 8];
                #pragma unroll
                for (int j = 0; j < 8; j++) {
                    int n = n0 + j * 8 + cq;
                    atomicMax(&g_pooled[sa  * LAT + n],     encf(acc3[i][j][0] + b3s[n]));
                    atomicMax(&g_pooled[sa  * LAT + n + 1], encf(acc3[i][j][1] + b3s[n + 1]));
                    atomicMax(&g_pooled[sbg * LAT + n],     encf(acc3[i][j][2] + b3s[n]));
                    atomicMax(&g_pooled[sbg * LAT + n + 1], encf(acc3[i][j][3] + b3s[n + 1]));
                }
            }
        }
    }
}

__global__ void k_final(const float* __restrict__ Wf,
                        const float* __restrict__ bf,
                        float* __restrict__ out) {
    int g = blockIdx.x, l = threadIdx.x;
    float a0 = 0.f, a1 = 0.f, a2 = 0.f;
    for (int j = l; j < LAT; j += 32) {
        float v = decf(g_pooled[g * LAT + j]);
        a0 = fmaf(v, Wf[j * 3 + 0], a0);
        a1 = fmaf(v, Wf[j * 3 + 1], a1);
        a2 = fmaf(v, Wf[j * 3 + 2], a2);
    }
    #pragma unroll
    for (int o = 16; o > 0; o >>= 1) {
        a0 += __shfl_down_sync(0xffffffffu, a0, o);
        a1 += __shfl_down_sync(0xffffffffu, a1, o);
        a2 += __shfl_down_sync(0xffffffffu, a2, o);
    }
    if (l == 0) {
        float inv = 1.f / fmaxf(g_cnt[g], 1.f);
        out[g * 3 + 0] = g_csum[g * 3 + 0] * inv + softplus_f(a0 + bf[0]);
        out[g * 3 + 1] = g_csum[g * 3 + 1] * inv + softplus_f(a1 + bf[1]);
        out[g * 3 + 2] = g_csum[g * 3 + 2] * inv + softplus_f(a2 + bf[2]);
    }
}

// ---------------- launch --------------------------------------------------
extern "C" void kernel_launch(void* const* d_in, const int* in_sizes, int n_in,
                              void* d_out, int out_size) {
    const float* pc = (const float*)d_in[0];
    const float* W1 = (const float*)d_in[1];
    const float* b1 = (const float*)d_in[2];
    const float* W2 = (const float*)d_in[3];
    const float* b2 = (const float*)d_in[4];
    const float* W3 = (const float*)d_in[5];
    const float* b3 = (const float*)d_in[6];
    const float* Wf = (const float*)d_in[7];
    const float* bf = (const float*)d_in[8];
    const int*   sg = (const int*)d_in[9];
    float* out = (float*)d_out;
    (void)in_sizes; (void)n_in; (void)out_size;

    cudaFuncSetAttribute(k_mlp, cudaFuncAttributeMaxDynamicSharedMemorySize,
                         SMEM_TOTAL);
    int sms = 148;
    cudaDeviceGetAttribute(&sms, cudaDevAttrMultiProcessorCount, 0);

    k_init<<<64, 256>>>();
    k_mlp<<<sms, 256, SMEM_TOTAL>>>(pc, W1, b1, W2, b2, W3, b3, sg);
    k_final<<<G, 32>>>(Wf, bf, out);
}

// round 6
// speedup vs baseline: 8.3575x; 1.2534x over previous
#include <cuda_runtime.h>
#include <cuda_fp16.h>
#include <cstdint>
#include <math.h>

#define N_PTS 1000000
#define G     256
#define H1C   64
#define H2C   128
#define LAT   256
#define TILE  64
#define NT    15625         // 1e6 / 64 exactly
#define THREADS 128

// ---------------- scratch -----------------------------------------------
__device__ unsigned g_pooled[G * LAT];
__device__ float    g_csum[G * 3];
__device__ float    g_cnt[G];

__device__ __forceinline__ unsigned encf(float f) {
    unsigned u = __float_as_uint(f);
    return (u & 0x80000000u) ? ~u : (u | 0x80000000u);
}
__device__ __forceinline__ float decf(unsigned u) {
    return (u & 0x80000000u) ? __uint_as_float(u ^ 0x80000000u)
                             : __uint_as_float(~u);
}
__device__ __forceinline__ float softplus_f(float x) {
    return fmaxf(x, 0.f) + log1pf(expf(-fabsf(x)));
}

// ---------------- mma.sync helpers --------------------------------------
__device__ __forceinline__ uint32_t smem_u32(const void* p) {
    uint32_t a;
    asm("{ .reg .u64 t; cvta.to.shared.u64 t, %1; cvt.u32.u64 %0, t; }"
        : "=r"(a) : "l"(p));
    return a;
}
__device__ __forceinline__ void ldsm4(uint32_t r[4], uint32_t a) {
    asm volatile("ldmatrix.sync.aligned.m8n8.x4.shared.b16 {%0,%1,%2,%3}, [%4];"
        : "=r"(r[0]), "=r"(r[1]), "=r"(r[2]), "=r"(r[3]) : "r"(a));
}
__device__ __forceinline__ void mma16816(float d[4], const uint32_t a[4],
                                         uint32_t b0, uint32_t b1) {
    asm volatile(
        "mma.sync.aligned.m16n8k16.row.col.f32.f16.f16.f32 "
        "{%0,%1,%2,%3}, {%4,%5,%6,%7}, {%8,%9}, {%0,%1,%2,%3};"
        : "+f"(d[0]), "+f"(d[1]), "+f"(d[2]), "+f"(d[3])
        : "r"(a[0]), "r"(a[1]), "r"(a[2]), "r"(a[3]), "r"(b0), "r"(b1));
}
__device__ __forceinline__ unsigned pack_f16(float lo, float hi) {
    unsigned r;
    asm("cvt.rn.f16x2.f32 %0, %1, %2;" : "=r"(r) : "f"(hi), "f"(lo));
    return r;  // low 16 bits = lo
}

// ---------------- SMEM layout (bytes; tiles 1024-aligned) ----------------
// Weight tiles [n][k] fp16, 128B rows (64 k per block), SW128 swizzle.
#define OFF_W3    0         // 2 kblk x 256 x 128B = 65536
#define OFF_W2    65536     // 128 x 128B = 16384
#define OFF_H1    81920     // 64 x 128B = 8192
#define OFF_H2    90112     // 2 kblk x 64 x 128B = 16384
#define OFF_FEATS 106496    // 64*4 f = 1024
#define OFF_W1    107520    // 256 f = 1024
#define OFF_B1    108544    // 256
#define OFF_B2    108800    // 512
#define OFF_B3    109312    // 1024
#define OFF_SEGS  110336    // 2 x 64 ints (double buffered) = 512
#define SMEM_TOTAL 110848   // x2 CTAs = 221696 <= 228KB/SM

// ---------------- kernels ------------------------------------------------
__global__ void k_init() {
    int i = blockIdx.x * blockDim.x + threadIdx.x;
    int stride = gridDim.x * blockDim.x;
    for (int j = i; j < G * LAT; j += stride) g_pooled[j] = 0u;
    if (i < G * 3) g_csum[i] = 0.f;
    if (i < G)     g_cnt[i]  = 0.f;
}

__global__ __launch_bounds__(THREADS, 2)
void k_mlp(const float* __restrict__ pc,
           const float* __restrict__ W1, const float* __restrict__ b1,
           const float* __restrict__ W2, const float* __restrict__ b2,
           const float* __restrict__ W3, const float* __restrict__ b3,
           const int*   __restrict__ seg) {
    extern __shared__ __align__(1024) char smem[];
    const uint32_t sb = smem_u32(smem);
    const int tid  = threadIdx.x;
    const int w    = tid >> 5;      // 4 warps
    const int lane = tid & 31;
    const bool is64 = (seg[N_PTS - 1] == 0);

    float* feats = (float*)(smem + OFF_FEATS);
    float* W1s   = (float*)(smem + OFF_W1);
    float* b1s   = (float*)(smem + OFF_B1);
    float* b2s   = (float*)(smem + OFF_B2);
    float* b3s   = (float*)(smem + OFF_B3);
    int*   segsA = (int*)  (smem + OFF_SEGS);
    int*   segsB = segsA + TILE;

    // ---- one-time weight prep: transpose to [n][k] fp16, SW128 ----------
    for (int i = tid; i < H1C * H2C; i += THREADS) {      // W2 [k=64][n=128]
        int k = i >> 7, n = i & 127;
        unsigned off = (unsigned)(n * 128) + (((unsigned)(k * 2)) ^ ((n & 7) << 4));
        *(__half*)(smem + OFF_W2 + off) = __float2half_rn(W2[i]);
    }
    for (int i = tid; i < H2C * LAT; i += THREADS) {      // W3 [k=128][n=256]
        int k = i >> 8, n = i & 255;
        unsigned off = (unsigned)((k >> 6) * 32768) + (unsigned)(n * 128)
                     + ((((unsigned)(k & 63)) * 2) ^ ((n & 7) << 4));
        *(__half*)(smem + OFF_W3 + off) = __float2half_rn(W3[i]);
    }
    for (int i = tid; i < 4 * H1C; i += THREADS) W1s[i] = W1[i];
    for (int i = tid; i < H1C;     i += THREADS) b1s[i] = b1[i];
    for (int i = tid; i < H2C;     i += THREADS) b2s[i] = b2[i];
    for (int i = tid; i < LAT;     i += THREADS) b3s[i] = b3[i];

    // per-lane ldmatrix geometry (validated layout)
    const int lane7 = lane & 7;
    const int gA_r = ((lane >> 3) & 1) * 8 + lane7;   // A row offset in 16x16
    const int gA_c = ((lane >> 4) & 1) * 8;           // A col offset
    const int gB_r = ((lane >> 4) & 1) * 8 + lane7;   // B n offset
    const int gB_c = ((lane >> 3) & 1) * 8;           // B k offset
    const unsigned xmA = (unsigned)lane7 << 4;        // swizzle (row&7)<<4
    const int rq = lane >> 2;                         // c-frag row-in-8
    const int cq = 2 * (lane & 3);                    // c-frag col pair

    int it = 0;
    for (int t = blockIdx.x; t < NT; t += gridDim.x, it++) {
        const long P0 = (long)t * TILE;
        int* segs = (it & 1) ? segsB : segsA;

        // ---- tile load + fused centroid (one thread per point) ----------
        if (tid < TILE) {
            const int p = tid;
            long gp = P0 + p;
            float c1 = pc[gp * 5 + 1];
            float c2 = pc[gp * 5 + 2];
            float c3 = pc[gp * 5 + 3];
            float c4 = pc[gp * 5 + 4];
            feats[p * 4 + 0] = c4;
            feats[p * 4 + 1] = c1;
            feats[p * 4 + 2] = c2;
            feats[p * 4 + 3] = c3;
            int s = is64 ? seg[2 * gp] : seg[gp];
            segs[p] = s;
            float x = c1, y = c2, z = c3, cn = 1.f;
            int s0 = __shfl_sync(0xffffffffu, s, 0);
            if (__all_sync(0xffffffffu, s == s0)) {
                #pragma unroll
                for (int o = 16; o > 0; o >>= 1) {
                    x  += __shfl_down_sync(0xffffffffu, x,  o);
                    y  += __shfl_down_sync(0xffffffffu, y,  o);
                    z  += __shfl_down_sync(0xffffffffu, z,  o);
                    cn += __shfl_down_sync(0xffffffffu, cn, o);
                }
                if (lane == 0) {
                    atomicAdd(&g_csum[s * 3 + 0], x);
                    atomicAdd(&g_csum[s * 3 + 1], y);
                    atomicAdd(&g_csum[s * 3 + 2], z);
                    atomicAdd(&g_cnt[s], cn);
                }
            } else {
                atomicAdd(&g_csum[s * 3 + 0], x);
                atomicAdd(&g_csum[s * 3 + 1], y);
                atomicAdd(&g_csum[s * 3 + 2], z);
                atomicAdd(&g_cnt[s], 1.f);
            }
        }
        __syncthreads();                     // sync1: feats/segs ready

        // ---- layer 1 (FFMA, K=4) -> h1 fp16, swizzled (2 thr/point)
        {
            int p = tid >> 1, q = tid & 1;
            float f0 = feats[p * 4 + 0], f1 = feats[p * 4 + 1];
            float f2 = feats[p * 4 + 2], f3 = feats[p * 4 + 3];
            unsigned rowb = (unsigned)(p * 128), xm = (unsigned)(p & 7) << 4;
            #pragma unroll
            for (int jj = 0; jj < 16; jj++) {
                int n = q * 32 + 2 * jj;
                float v0 = b1s[n];
                v0 = fmaf(f0, W1s[n], v0);       v0 = fmaf(f1, W1s[64 + n], v0);
                v0 = fmaf(f2, W1s[128 + n], v0); v0 = fmaf(f3, W1s[192 + n], v0);
                float v1 = b1s[n + 1];
                v1 = fmaf(f0, W1s[n + 1], v1);       v1 = fmaf(f1, W1s[65 + n], v1);
                v1 = fmaf(f2, W1s[129 + n], v1);     v1 = fmaf(f3, W1s[193 + n], v1);
                v0 = fmaxf(v0, 0.f); v1 = fmaxf(v1, 0.f);
                unsigned off = rowb + (((unsigned)(n * 2)) ^ xm);
                *(unsigned*)(smem + OFF_H1 + off) = pack_f16(v0, v1);
            }
        }
        __syncthreads();                     // sync2: h1 ready

        // ---- layer 2: C2(64x128) = h1 @ W2; warp = (64 rows, 32 n)
        {
            float acc[4][4][4];
            #pragma unroll
            for (int i = 0; i < 4; i++)
                #pragma unroll
                for (int j = 0; j < 4; j++)
                    #pragma unroll
                    for (int q = 0; q < 4; q++) acc[i][j][q] = 0.f;
            const int n0 = w * 32;
            #pragma unroll
            for (int kt = 0; kt < 4; kt++) {
                const int k0 = kt * 16;
                uint32_t Bh[2][4];
                #pragma unroll
                for (int nb = 0; nb < 2; nb++) {
                    unsigned boff = (unsigned)((n0 + nb * 16 + gB_r) * 128)
                                  + (((unsigned)((k0 + gB_c) * 2)) ^ xmA);
                    ldsm4(Bh[nb], sb + OFF_W2 + boff);
                }
                #pragma unroll
                for (int i = 0; i < 4; i++) {
                    uint32_t Ah[4];
                    unsigned aoff = (unsigned)((i * 16 + gA_r) * 128)
                                  + (((unsigned)((k0 + gA_c) * 2)) ^ xmA);
                    ldsm4(Ah, sb + OFF_H1 + aoff);
                    #pragma unroll
                    for (int nb = 0; nb < 2; nb++) {
                        mma16816(acc[i][2 * nb + 0], Ah, Bh[nb][0], Bh[nb][1]);
                        mma16816(acc[i][2 * nb + 1], Ah, Bh[nb][2], Bh[nb][3]);
                    }
                }
            }
            // epilogue: bias+relu -> h2 fp16 (n becomes k)
            #pragma unroll
            for (int i = 0; i < 4; i++)
                #pragma unroll
                for (int j = 0; j < 4; j++) {
                    int n = n0 + j * 8 + cq;
                    float v0 = fmaxf(acc[i][j][0] + b2s[n],     0.f);
                    float v1 = fmaxf(acc[i][j][1] + b2s[n + 1], 0.f);
                    float v2 = fmaxf(acc[i][j][2] + b2s[n],     0.f);
                    float v3 = fmaxf(acc[i][j][3] + b2s[n + 1], 0.f);
                    unsigned blk = (unsigned)((n >> 6) * 8192);
                    int r0 = i * 16 + rq;
                    unsigned cbyte = ((unsigned)((n & 63) * 2))
                                   ^ ((unsigned)rq << 4);
                    *(unsigned*)(smem + OFF_H2 + blk + (unsigned)(r0 * 128) + cbyte)
                        = pack_f16(v0, v1);
                    *(unsigned*)(smem + OFF_H2 + blk + (unsigned)((r0 + 8) * 128) + cbyte)
                        = pack_f16(v2, v3);
                }
        }
        __syncthreads();                     // sync3: h2 ready

        // ---- layer 3: C3(64x256) = h2 @ W3; warp = (64 rows, 64 n)
        float acc3[4][8][4];
        #pragma unroll
        for (int i = 0; i < 4; i++)
            #pragma unroll
            for (int j = 0; j < 8; j++)
                #pragma unroll
                for (int q = 0; q < 4; q++) acc3[i][j][q] = 0.f;
        const int n0 = w * 64;
        #pragma unroll
        for (int kt = 0; kt < 8; kt++) {
            const int k0 = kt * 16;
            const unsigned kbA = (unsigned)((k0 >> 6) * 8192);
            const unsigned kbB = (unsigned)((k0 >> 6) * 32768);
            const unsigned kby = ((unsigned)(((k0 & 63) + gB_c) * 2)) ^ xmA;
            const unsigned kay = ((unsigned)(((k0 & 63) + gA_c) * 2)) ^ xmA;
            uint32_t Bh[4][4];
            #pragma unroll
            for (int nb = 0; nb < 4; nb++) {
                unsigned boff = kbB + (unsigned)((n0 + nb * 16 + gB_r) * 128) + kby;
                ldsm4(Bh[nb], sb + OFF_W3 + boff);
            }
            #pragma unroll
            for (int i = 0; i < 4; i++) {
                uint32_t Ah[4];
                ldsm4(Ah, sb + OFF_H2 + kbA
                      + (unsigned)((i * 16 + gA_r) * 128) + kay);
                #pragma unroll
                for (int nb = 0; nb < 4; nb++) {
                    mma16816(acc3[i][2 * nb + 0], Ah, Bh[nb][0], Bh[nb][1]);
                    mma16816(acc3[i][2 * nb + 1], Ah, Bh[nb][2], Bh[nb][3]);
                }
            }
        }

        // ---- segment-max pooling epilogue
        if (segs[0] == segs[TILE - 1]) {
            const int s0 = segs[0];
            #pragma unroll
            for (int j = 0; j < 8; j++) {
                float v0 = -3.402823466e38f, v1 = -3.402823466e38f;
                #pragma unroll
                for (int i = 0; i < 4; i++) {
                    v0 = fmaxf(v0, fmaxf(acc3[i][j][0], acc3[i][j][2]));
                    v1 = fmaxf(v1, fmaxf(acc3[i][j][1], acc3[i][j][3]));
                }
                #pragma unroll
                for (int o = 4; o < 32; o <<= 1) {
                    v0 = fmaxf(v0, __shfl_xor_sync(0xffffffffu, v0, o));
                    v1 = fmaxf(v1, __shfl_xor_sync(0xffffffffu, v1, o));
                }
                if (lane < 4) {
                    int n = n0 + j * 8 + cq;
                    atomicMax(&g_pooled[s0 * LAT + n],     encf(v0 + b3s[n]));
                    atomicMax(&g_pooled[s0 * LAT + n + 1], encf(v1 + b3s[n + 1]));
                }
            }
        } else {
            #pragma unroll
            for (int i = 0; i < 4; i++) {
                int r0 = i * 16 + rq;
                int sa = segs[r0], sbg = segs[r0 + 8];
                #pragma unroll
                for (int j = 0; j < 8; j++) {
                    int n = n0 + j * 8 + cq;
                    atomicMax(&g_pooled[sa  * LAT + n],     encf(acc3[i][j][0] + b3s[n]));
                    atomicMax(&g_pooled[sa  * LAT + n + 1], encf(acc3[i][j][1] + b3s[n + 1]));
                    atomicMax(&g_pooled[sbg * LAT + n],     encf(acc3[i][j][2] + b3s[n]));
                    atomicMax(&g_pooled[sbg * LAT + n + 1], encf(acc3[i][j][3] + b3s[n + 1]));
                }
            }
        }
    }
}

__global__ void k_final(const float* __restrict__ Wf,
                        const float* __restrict__ bf,
                        float* __restrict__ out) {
    int g = blockIdx.x, l = threadIdx.x;
    float a0 = 0.f, a1 = 0.f, a2 = 0.f;
    for (int j = l; j < LAT; j += 32) {
        float v = decf(g_pooled[g * LAT + j]);
        a0 = fmaf(v, Wf[j * 3 + 0], a0);
        a1 = fmaf(v, Wf[j * 3 + 1], a1);
        a2 = fmaf(v, Wf[j * 3 + 2], a2);
    }
    #pragma unroll
    for (int o = 16; o > 0; o >>= 1) {
        a0 += __shfl_down_sync(0xffffffffu, a0, o);
        a1 += __shfl_down_sync(0xffffffffu, a1, o);
        a2 += __shfl_down_sync(0xffffffffu, a2, o);
    }
    if (l == 0) {
        float inv = 1.f / fmaxf(g_cnt[g], 1.f);
        out[g * 3 + 0] = g_csum[g * 3 + 0] * inv + softplus_f(a0 + bf[0]);
        out[g * 3 + 1] = g_csum[g * 3 + 1] * inv + softplus_f(a1 + bf[1]);
        out[g * 3 + 2] = g_csum[g * 3 + 2] * inv + softplus_f(a2 + bf[2]);
    }
}

// ---------------- launch --------------------------------------------------
extern "C" void kernel_launch(void* const* d_in, const int* in_sizes, int n_in,
                              void* d_out, int out_size) {
    const float* pc = (const float*)d_in[0];
    const float* W1 = (const float*)d_in[1];
    const float* b1 = (const float*)d_in[2];
    const float* W2 = (const float*)d_in[3];
    const float* b2 = (const float*)d_in[4];
    const float* W3 = (const float*)d_in[5];
    const float* b3 = (const float*)d_in[6];
    const float* Wf = (const float*)d_in[7];
    const float* bf = (const float*)d_in[8];
    const int*   sg = (const int*)d_in[9];
    float* out = (float*)d_out;
    (void)in_sizes; (void)n_in; (void)out_size;

    cudaFuncSetAttribute(k_mlp, cudaFuncAttributeMaxDynamicSharedMemorySize,
                         SMEM_TOTAL);
    int sms = 148;
    cudaDeviceGetAttribute(&sms, cudaDevAttrMultiProcessorCount, 0);

    k_init<<<64, 256>>>();
    k_mlp<<<sms * 2, THREADS, SMEM_TOTAL>>>(pc, W1, b1, W2, b2, W3, b3, sg);
    k_final<<<G, 32>>>(Wf, bf, out);
}